// round 1
// baseline (speedup 1.0000x reference)
#include <cuda_runtime.h>

// Problem constants (fixed-shape instance)
#define EMSG  131072      // messages
#define NNODE 8192        // nodes
#define DDIM  256         // feature dim
#define GG    16          // nodes per block (lockstep group)
#define NGRP  (NNODE/GG)  // 512 groups
#define NB    512         // count-sort bins
#define CHK   16          // W k-chunk rows staged in smem

// ---------------- device scratch (static, no allocation) ----------------
__device__ int   g_counts [NNODE];
__device__ int   g_offsets[NNODE];
__device__ int   g_cursor [NNODE];
__device__ int   g_ids    [EMSG];
__device__ float g_tk     [EMSG];
__device__ int   g_order  [NNODE];
__device__ int   g_kbins  [NB];
__device__ int   g_koff   [NB];
__device__ int   g_kcur   [NB];
__device__ __align__(16) float g_Wt[DDIM*DDIM];   // W transposed: Wt[k][j] = W[j][k]

// ---------------- setup kernels ----------------
__global__ void k_init() {
    int i = blockIdx.x * blockDim.x + threadIdx.x;
    if (i < NNODE) { g_counts[i] = 0; g_cursor[i] = 0; }
    if (i < NB)    { g_kbins[i]  = 0; g_kcur[i]   = 0; }
}

__global__ void k_hist(const int* __restrict__ idx) {
    int e = blockIdx.x * blockDim.x + threadIdx.x;
    if (e < EMSG) atomicAdd(&g_counts[idx[e]], 1);
}

// exclusive scan over 8192 counts, single block of 1024 threads (8 per thread)
__global__ void k_scan() {
    __shared__ int part[1024];
    int tid  = threadIdx.x;
    int base = tid * 8;
    int loc[8]; int s = 0;
#pragma unroll
    for (int j = 0; j < 8; j++) { loc[j] = g_counts[base + j]; s += loc[j]; }
    part[tid] = s; __syncthreads();
    for (int off = 1; off < 1024; off <<= 1) {
        int v = (tid >= off) ? part[tid - off] : 0;
        __syncthreads();
        part[tid] += v;
        __syncthreads();
    }
    int run = (tid > 0) ? part[tid - 1] : 0;
#pragma unroll
    for (int j = 0; j < 8; j++) { g_offsets[base + j] = run; run += loc[j]; }
}

__global__ void k_scatter(const int* __restrict__ idx, const float* __restrict__ t) {
    int e = blockIdx.x * blockDim.x + threadIdx.x;
    if (e < EMSG) {
        int n    = idx[e];
        int p    = atomicAdd(&g_cursor[n], 1);
        int slot = g_offsets[n] + p;
        g_ids[slot] = e;
        g_tk[slot]  = t[e];
    }
}

// per-node insertion sort by (t, msg_id) -- matches jnp.lexsort stability
__global__ void k_sortnode() {
    int n = blockIdx.x * blockDim.x + threadIdx.x;
    if (n >= NNODE) return;
    int base = g_offsets[n], K = g_counts[n];
    for (int i = 1; i < K; i++) {
        float tv = g_tk[base + i]; int iv = g_ids[base + i];
        int j = i - 1;
        while (j >= 0) {
            float tj = g_tk[base + j]; int ij = g_ids[base + j];
            if (tj > tv || (tj == tv && ij > iv)) {
                g_tk[base + j + 1] = tj; g_ids[base + j + 1] = ij; j--;
            } else break;
        }
        g_tk[base + j + 1] = tv; g_ids[base + j + 1] = iv;
    }
}

// counting sort of node ids by message count (for lockstep balance)
__global__ void k_kbhist() {
    int n = blockIdx.x * blockDim.x + threadIdx.x;
    if (n < NNODE) {
        int kb = min(g_counts[n], NB - 1);
        atomicAdd(&g_kbins[kb], 1);
    }
}
__global__ void k_kscan() {   // 1 block, NB threads
    __shared__ int part[NB];
    int tid = threadIdx.x;
    part[tid] = g_kbins[tid]; __syncthreads();
    for (int off = 1; off < NB; off <<= 1) {
        int v = (tid >= off) ? part[tid - off] : 0;
        __syncthreads();
        part[tid] += v;
        __syncthreads();
    }
    g_koff[tid] = (tid > 0) ? part[tid - 1] : 0;
}
__global__ void k_korder() {
    int n = blockIdx.x * blockDim.x + threadIdx.x;
    if (n < NNODE) {
        int kb = min(g_counts[n], NB - 1);
        int p  = atomicAdd(&g_kcur[kb], 1);
        g_order[g_koff[kb] + p] = n;
    }
}

__global__ void k_transpose(const float* __restrict__ W) {
    int i = blockIdx.x * blockDim.x + threadIdx.x;   // over 65536
    int k = i >> 8, j = i & 255;
    g_Wt[k * DDIM + j] = W[j * DDIM + k];            // coalesced write
}

// ---------------- main lockstep recurrence kernel ----------------
// X stored transposed in smem as sX[k][r] with a 4-row-group XOR swizzle to
// avoid 32-way STS conflicts during the X build while keeping float4 reads.
__device__ __forceinline__ int sxIdx(int k, int r) {
    return k * GG + (((((r >> 2) ^ ((k >> 2) & 3))) << 2) | (r & 3));
}

__global__ void __launch_bounds__(256) k_main(const float* __restrict__ msg,
                                              const float* __restrict__ b,
                                              float* __restrict__ out) {
    __shared__ __align__(16) float sX[DDIM * GG];   // 16 KB, X^T swizzled
    __shared__ __align__(16) float sW[CHK * DDIM];  // 16 KB, Wt chunk
    __shared__ int sNode[GG], sK[GG], sOff[GG];
    __shared__ int sKmax;

    int tid = threadIdx.x;
    int cx  = tid & 63;      // column tile: cols [cx*4, cx*4+4)
    int ry  = tid >> 6;      // row tile:    rows [ry*4, ry*4+4)
    int gidx = (NGRP - 1) - blockIdx.x;   // biggest-K groups first

    if (tid < GG) {
        int n = g_order[gidx * GG + tid];
        sNode[tid] = n; sK[tid] = g_counts[n]; sOff[tid] = g_offsets[n];
    }
    __syncthreads();
    if (tid == 0) {
        int m = 0;
        for (int r = 0; r < GG; r++) m = max(m, sK[r]);
        sKmax = m;
    }
    __syncthreads();

    float h[4][4];
#pragma unroll
    for (int rr = 0; rr < 4; rr++)
#pragma unroll
        for (int cc = 0; cc < 4; cc++) h[rr][cc] = 0.0f;

    float4 bb = ((const float4*)b)[cx];

    int myK[4], myOff[4];
#pragma unroll
    for (int rr = 0; rr < 4; rr++) {
        int r = ry * 4 + rr;
        myK[rr]  = sK[r];
        myOff[rr] = sOff[r];
    }
    int Kmax = sKmax;
    const float4* msg4 = (const float4*)msg;

    for (int s = 0; s < Kmax; ++s) {
        // ---- build X = m_s + h for active rows (others stale; results discarded)
#pragma unroll
        for (int rr = 0; rr < 4; rr++) {
            if (s < myK[rr]) {
                int row = ry * 4 + rr;
                int id  = g_ids[myOff[rr] + s];
                float4 mv = msg4[id * 64 + cx];
                int k0 = cx * 4;
                sX[sxIdx(k0 + 0, row)] = mv.x + h[rr][0];
                sX[sxIdx(k0 + 1, row)] = mv.y + h[rr][1];
                sX[sxIdx(k0 + 2, row)] = mv.z + h[rr][2];
                sX[sxIdx(k0 + 3, row)] = mv.w + h[rr][3];
            }
        }
        __syncthreads();

        // ---- Y[16][256] = X[16][256] @ Wt[256][256], Wt streamed through smem
        float acc[4][4];
#pragma unroll
        for (int rr = 0; rr < 4; rr++)
#pragma unroll
            for (int cc = 0; cc < 4; cc++) acc[rr][cc] = 0.0f;

        for (int kc = 0; kc < DDIM; kc += CHK) {
#pragma unroll
            for (int u = 0; u < 4; u++) {
                int lin = u * 256 + tid;                        // float4 slot
                ((float4*)sW)[lin] = ((const float4*)g_Wt)[kc * 64 + lin];
            }
            __syncthreads();
#pragma unroll
            for (int kk = 0; kk < CHK; kk++) {
                int k = kc + kk;
                float4 xv = *(const float4*)&sX[k * GG + ((ry ^ ((k >> 2) & 3)) << 2)];
                float4 wv = *(const float4*)&sW[kk * DDIM + cx * 4];
                float xr[4] = {xv.x, xv.y, xv.z, xv.w};
                float wc[4] = {wv.x, wv.y, wv.z, wv.w};
#pragma unroll
                for (int rr = 0; rr < 4; rr++)
#pragma unroll
                    for (int cc = 0; cc < 4; cc++)
                        acc[rr][cc] += xr[rr] * wc[cc];
            }
            __syncthreads();
        }

        // ---- h update only for active rows (inactive keep previous h)
#pragma unroll
        for (int rr = 0; rr < 4; rr++) {
            if (s < myK[rr]) {
                h[rr][0] = acc[rr][0] + bb.x;
                h[rr][1] = acc[rr][1] + bb.y;
                h[rr][2] = acc[rr][2] + bb.z;
                h[rr][3] = acc[rr][3] + bb.w;
            }
        }
    }

    // ---- write final hidden state (zeros for K=0 nodes)
#pragma unroll
    for (int rr = 0; rr < 4; rr++) {
        int row = ry * 4 + rr;
        int n   = sNode[row];
        ((float4*)out)[n * 64 + cx] =
            make_float4(h[rr][0], h[rr][1], h[rr][2], h[rr][3]);
    }
}

// ---------------- launch ----------------
extern "C" void kernel_launch(void* const* d_in, const int* in_sizes, int n_in,
                              void* d_out, int out_size) {
    const float* msg = nullptr;
    const int*   idx = nullptr;
    const float* t   = nullptr;
    const float* W   = nullptr;
    const float* b   = nullptr;
    int seenE = 0;
    for (int i = 0; i < n_in; i++) {
        long sz = in_sizes[i];
        if (sz == (long)EMSG * DDIM)      msg = (const float*)d_in[i];
        else if (sz == EMSG) {
            if (seenE == 0) idx = (const int*)d_in[i];
            else            t   = (const float*)d_in[i];
            seenE++;
        }
        else if (sz == DDIM * DDIM)       W = (const float*)d_in[i];
        else if (sz == DDIM)              b = (const float*)d_in[i];
        // sz == 1 (dim_size scalar) ignored — N is fixed
    }

    k_init    <<<32,  256>>>();
    k_hist    <<<512, 256>>>(idx);
    k_scan    <<<1,  1024>>>();
    k_scatter <<<512, 256>>>(idx, t);
    k_sortnode<<<32,  256>>>();
    k_kbhist  <<<32,  256>>>();
    k_kscan   <<<1,    NB>>>();
    k_korder  <<<32,  256>>>();
    k_transpose<<<256,256>>>(W);
    k_main    <<<NGRP,256>>>(msg, b, (float*)d_out);
}

// round 2
// speedup vs baseline: 1.0054x; 1.0054x over previous
#include <cuda_runtime.h>

// Problem constants (fixed-shape instance)
#define EMSG  131072      // messages
#define NNODE 8192        // nodes
#define DDIM  256         // feature dim
#define GG    16          // nodes per block (lockstep group)
#define NGRP  (NNODE/GG)  // 512 groups
#define NB    512         // count-sort bins
#define CHK   16          // W k-chunk rows staged in smem

// ---------------- device scratch (static, no allocation) ----------------
__device__ int   g_counts [NNODE];
__device__ int   g_offsets[NNODE];
__device__ int   g_cursor [NNODE];
__device__ int   g_ids    [EMSG];
__device__ float g_tk     [EMSG];
__device__ int   g_order  [NNODE];
__device__ int   g_kbins  [NB];
__device__ int   g_koff   [NB];
__device__ int   g_kcur   [NB];
__device__ __align__(16) float g_Wt[DDIM*DDIM];   // W transposed: Wt[k][j] = W[j][k]

// ---------------- setup kernels ----------------
__global__ void k_init() {
    int i = blockIdx.x * blockDim.x + threadIdx.x;
    if (i < NNODE) { g_counts[i] = 0; g_cursor[i] = 0; }
    if (i < NB)    { g_kbins[i]  = 0; g_kcur[i]   = 0; }
}

__global__ void k_hist(const int* __restrict__ idx) {
    int e = blockIdx.x * blockDim.x + threadIdx.x;
    if (e < EMSG) atomicAdd(&g_counts[idx[e]], 1);
}

// exclusive scan over 8192 counts, single block of 1024 threads (8 per thread)
__global__ void k_scan() {
    __shared__ int part[1024];
    int tid  = threadIdx.x;
    int base = tid * 8;
    int loc[8]; int s = 0;
#pragma unroll
    for (int j = 0; j < 8; j++) { loc[j] = g_counts[base + j]; s += loc[j]; }
    part[tid] = s; __syncthreads();
    for (int off = 1; off < 1024; off <<= 1) {
        int v = (tid >= off) ? part[tid - off] : 0;
        __syncthreads();
        part[tid] += v;
        __syncthreads();
    }
    int run = (tid > 0) ? part[tid - 1] : 0;
#pragma unroll
    for (int j = 0; j < 8; j++) { g_offsets[base + j] = run; run += loc[j]; }
}

__global__ void k_scatter(const int* __restrict__ idx, const float* __restrict__ t) {
    int e = blockIdx.x * blockDim.x + threadIdx.x;
    if (e < EMSG) {
        int n    = idx[e];
        int p    = atomicAdd(&g_cursor[n], 1);
        int slot = g_offsets[n] + p;
        g_ids[slot] = e;
        g_tk[slot]  = t[e];
    }
}

// per-node insertion sort by (t, msg_id) -- matches jnp.lexsort stability
__global__ void k_sortnode() {
    int n = blockIdx.x * blockDim.x + threadIdx.x;
    if (n >= NNODE) return;
    int base = g_offsets[n], K = g_counts[n];
    for (int i = 1; i < K; i++) {
        float tv = g_tk[base + i]; int iv = g_ids[base + i];
        int j = i - 1;
        while (j >= 0) {
            float tj = g_tk[base + j]; int ij = g_ids[base + j];
            if (tj > tv || (tj == tv && ij > iv)) {
                g_tk[base + j + 1] = tj; g_ids[base + j + 1] = ij; j--;
            } else break;
        }
        g_tk[base + j + 1] = tv; g_ids[base + j + 1] = iv;
    }
}

// counting sort of node ids by message count (for lockstep balance)
__global__ void k_kbhist() {
    int n = blockIdx.x * blockDim.x + threadIdx.x;
    if (n < NNODE) {
        int kb = min(g_counts[n], NB - 1);
        atomicAdd(&g_kbins[kb], 1);
    }
}
__global__ void k_kscan() {   // 1 block, NB threads
    __shared__ int part[NB];
    int tid = threadIdx.x;
    part[tid] = g_kbins[tid]; __syncthreads();
    for (int off = 1; off < NB; off <<= 1) {
        int v = (tid >= off) ? part[tid - off] : 0;
        __syncthreads();
        part[tid] += v;
        __syncthreads();
    }
    g_koff[tid] = (tid > 0) ? part[tid - 1] : 0;
}
__global__ void k_korder() {
    int n = blockIdx.x * blockDim.x + threadIdx.x;
    if (n < NNODE) {
        int kb = min(g_counts[n], NB - 1);
        int p  = atomicAdd(&g_kcur[kb], 1);
        g_order[g_koff[kb] + p] = n;
    }
}

__global__ void k_transpose(const float* __restrict__ W) {
    int i = blockIdx.x * blockDim.x + threadIdx.x;   // over 65536
    int k = i >> 8, j = i & 255;
    g_Wt[k * DDIM + j] = W[j * DDIM + k];            // coalesced write
}

// ---------------- main lockstep recurrence kernel ----------------
// X stored transposed in smem as sX[k][r] with a 4-row-group XOR swizzle to
// avoid 32-way STS conflicts during the X build while keeping float4 reads.
__device__ __forceinline__ int sxIdx(int k, int r) {
    return k * GG + (((((r >> 2) ^ ((k >> 2) & 3))) << 2) | (r & 3));
}

__global__ void __launch_bounds__(256) k_main(const float* __restrict__ msg,
                                              const float* __restrict__ b,
                                              float* __restrict__ out) {
    __shared__ __align__(16) float sX[DDIM * GG];   // 16 KB, X^T swizzled
    __shared__ __align__(16) float sW[CHK * DDIM];  // 16 KB, Wt chunk
    __shared__ int sNode[GG], sK[GG], sOff[GG];
    __shared__ int sKmax;

    int tid = threadIdx.x;
    int cx  = tid & 63;      // column tile: cols [cx*4, cx*4+4)
    int ry  = tid >> 6;      // row tile:    rows [ry*4, ry*4+4)
    int gidx = (NGRP - 1) - blockIdx.x;   // biggest-K groups first

    if (tid < GG) {
        int n = g_order[gidx * GG + tid];
        sNode[tid] = n; sK[tid] = g_counts[n]; sOff[tid] = g_offsets[n];
    }
    __syncthreads();
    if (tid == 0) {
        int m = 0;
        for (int r = 0; r < GG; r++) m = max(m, sK[r]);
        sKmax = m;
    }
    __syncthreads();

    float h[4][4];
#pragma unroll
    for (int rr = 0; rr < 4; rr++)
#pragma unroll
        for (int cc = 0; cc < 4; cc++) h[rr][cc] = 0.0f;

    float4 bb = ((const float4*)b)[cx];

    int myK[4], myOff[4];
#pragma unroll
    for (int rr = 0; rr < 4; rr++) {
        int r = ry * 4 + rr;
        myK[rr]  = sK[r];
        myOff[rr] = sOff[r];
    }
    int Kmax = sKmax;
    const float4* msg4 = (const float4*)msg;

    for (int s = 0; s < Kmax; ++s) {
        // ---- build X = m_s + h for active rows (others stale; results discarded)
#pragma unroll
        for (int rr = 0; rr < 4; rr++) {
            if (s < myK[rr]) {
                int row = ry * 4 + rr;
                int id  = g_ids[myOff[rr] + s];
                float4 mv = msg4[id * 64 + cx];
                int k0 = cx * 4;
                sX[sxIdx(k0 + 0, row)] = mv.x + h[rr][0];
                sX[sxIdx(k0 + 1, row)] = mv.y + h[rr][1];
                sX[sxIdx(k0 + 2, row)] = mv.z + h[rr][2];
                sX[sxIdx(k0 + 3, row)] = mv.w + h[rr][3];
            }
        }
        __syncthreads();

        // ---- Y[16][256] = X[16][256] @ Wt[256][256], Wt streamed through smem
        float acc[4][4];
#pragma unroll
        for (int rr = 0; rr < 4; rr++)
#pragma unroll
            for (int cc = 0; cc < 4; cc++) acc[rr][cc] = 0.0f;

        for (int kc = 0; kc < DDIM; kc += CHK) {
#pragma unroll
            for (int u = 0; u < 4; u++) {
                int lin = u * 256 + tid;                        // float4 slot
                ((float4*)sW)[lin] = ((const float4*)g_Wt)[kc * 64 + lin];
            }
            __syncthreads();
#pragma unroll
            for (int kk = 0; kk < CHK; kk++) {
                int k = kc + kk;
                float4 xv = *(const float4*)&sX[k * GG + ((ry ^ ((k >> 2) & 3)) << 2)];
                float4 wv = *(const float4*)&sW[kk * DDIM + cx * 4];
                float xr[4] = {xv.x, xv.y, xv.z, xv.w};
                float wc[4] = {wv.x, wv.y, wv.z, wv.w};
#pragma unroll
                for (int rr = 0; rr < 4; rr++)
#pragma unroll
                    for (int cc = 0; cc < 4; cc++)
                        acc[rr][cc] += xr[rr] * wc[cc];
            }
            __syncthreads();
        }

        // ---- h update only for active rows (inactive keep previous h)
#pragma unroll
        for (int rr = 0; rr < 4; rr++) {
            if (s < myK[rr]) {
                h[rr][0] = acc[rr][0] + bb.x;
                h[rr][1] = acc[rr][1] + bb.y;
                h[rr][2] = acc[rr][2] + bb.z;
                h[rr][3] = acc[rr][3] + bb.w;
            }
        }
    }

    // ---- write final hidden state (zeros for K=0 nodes)
#pragma unroll
    for (int rr = 0; rr < 4; rr++) {
        int row = ry * 4 + rr;
        int n   = sNode[row];
        ((float4*)out)[n * 64 + cx] =
            make_float4(h[rr][0], h[rr][1], h[rr][2], h[rr][3]);
    }
}

// ---------------- launch ----------------
extern "C" void kernel_launch(void* const* d_in, const int* in_sizes, int n_in,
                              void* d_out, int out_size) {
    const float* msg = nullptr;
    const int*   idx = nullptr;
    const float* t   = nullptr;
    const float* W   = nullptr;
    const float* b   = nullptr;
    int seenE = 0;
    for (int i = 0; i < n_in; i++) {
        long sz = in_sizes[i];
        if (sz == (long)EMSG * DDIM)      msg = (const float*)d_in[i];
        else if (sz == EMSG) {
            if (seenE == 0) idx = (const int*)d_in[i];
            else            t   = (const float*)d_in[i];
            seenE++;
        }
        else if (sz == DDIM * DDIM)       W = (const float*)d_in[i];
        else if (sz == DDIM)              b = (const float*)d_in[i];
        // sz == 1 (dim_size scalar) ignored — N is fixed
    }

    k_init    <<<32,  256>>>();
    k_hist    <<<512, 256>>>(idx);
    k_scan    <<<1,  1024>>>();
    k_scatter <<<512, 256>>>(idx, t);
    k_sortnode<<<32,  256>>>();
    k_kbhist  <<<32,  256>>>();
    k_kscan   <<<1,    NB>>>();
    k_korder  <<<32,  256>>>();
    k_transpose<<<256,256>>>(W);
    k_main    <<<NGRP,256>>>(msg, b, (float*)d_out);
}